// round 11
// baseline (speedup 1.0000x reference)
#include <cuda_runtime.h>
#include <cuda_fp16.h>
#include <cuda_bf16.h>

#define D 128
#define NN 50000
#define NS 20000
#define NE 600000
#define ES 120000
#define CAP 64

// Feature buffers
__device__ float g_agg [(size_t)NN * D];
__device__ float g_h   [(size_t)NN * D];
__device__ float g_h1  [(size_t)NN * D];
__device__ float g_sub [(size_t)NS * D];

// Combined weights Wc = Wn2s @ Ws2n (fp32, per level) + deg-bias vectors
__device__ float g_Wc[2 * 128 * 128];
__device__ float g_dvec[2 * 128];

// Bucket CSR scratch: cnt contiguous (one memset), slots per phase
#define C_NE   0
#define C_S2N0 (NN)
#define C_S2N1 (2 * NN)
#define C_N2S0 (3 * NN)
#define C_N2S1 (3 * NN + NS)
__device__ int g_cnt[3 * NN + 2 * NS];
__device__ int g_slotNE  [(size_t)NN * CAP];
__device__ int g_slotS2N0[(size_t)NN * CAP];
__device__ int g_slotS2N1[(size_t)NN * CAP];
__device__ int g_slotN2S0[(size_t)NS * CAP];
__device__ int g_slotN2S1[(size_t)NS * CAP];

// Precomputed fp16 hi/lo W splits (smem layout): 0=Wm, 1=Wc0, 2=Wc1
#define WS_STRIDE 136
#define WS_WORDS  (64 * WS_STRIDE)
__device__ unsigned g_Whi[3 * WS_WORDS];
__device__ unsigned g_Wlo[3 * WS_WORDS];

// ---------------------------------------------------------------------------
// Prep: combined weights Wc = A@B and dvec = b@B, one kernel
// blockIdx.x in [0,128] : rows 0..127 -> Wc row; row 128 -> dvec
// ---------------------------------------------------------------------------
__global__ void wcdvec_k(const float* __restrict__ A0, const float* __restrict__ B0,
                         const float* __restrict__ b0,
                         const float* __restrict__ A1, const float* __restrict__ B1,
                         const float* __restrict__ b1)
{
    __shared__ float a[128];
    int lvl = blockIdx.y;
    const float* A = lvl ? A1 : A0;
    const float* B = lvl ? B1 : B0;
    const float* b = lvl ? b1 : b0;
    int i = blockIdx.x, j = threadIdx.x;
    a[j] = (i < 128) ? A[i * 128 + j] : b[j];
    __syncthreads();
    float acc = 0.f;
    #pragma unroll 8
    for (int k = 0; k < 128; k++) acc += a[k] * B[k * 128 + j];
    if (i < 128) g_Wc[lvl * 16384 + i * 128 + j] = acc;
    else         g_dvec[lvl * 128 + j] = acc;
}

// ---------------------------------------------------------------------------
// Merged bucket fill: blockIdx.y = phase (0=NE, 1..4=ES), grid-stride loop
// ---------------------------------------------------------------------------
__global__ void fill_all_k(const int* __restrict__ nei,
                           const int* __restrict__ r0, const int* __restrict__ c0,
                           const int* __restrict__ r1, const int* __restrict__ c1)
{
    int ph = blockIdx.y;
    const int* gi; const int* si; int cbase; int* slot; int n;
    switch (ph) {
        case 0:  gi = nei; si = nei + NE; cbase = C_NE;   slot = g_slotNE;   n = NE; break;
        case 1:  gi = r0;  si = c0;       cbase = C_N2S0; slot = g_slotN2S0; n = ES; break;
        case 2:  gi = c0;  si = r0;       cbase = C_S2N0; slot = g_slotS2N0; n = ES; break;
        case 3:  gi = r1;  si = c1;       cbase = C_N2S1; slot = g_slotN2S1; n = ES; break;
        default: gi = c1;  si = r1;       cbase = C_S2N1; slot = g_slotS2N1; n = ES; break;
    }
    int stride = gridDim.x * blockDim.x;
    for (int e = blockIdx.x * blockDim.x + threadIdx.x; e < n; e += stride) {
        int s = si[e];
        int p = atomicAdd(&g_cnt[cbase + s], 1);
        if (p < CAP) slot[(size_t)s * CAP + p] = gi[e];
    }
}

// ---------------------------------------------------------------------------
// Warp-per-node gather reduce, MLP-8 (int4 index prefetch + 8 gathers in flight)
// ---------------------------------------------------------------------------
__global__ void reduce_k(const float* __restrict__ feat,
                         const int* __restrict__ cnt, const int* __restrict__ slot,
                         float* __restrict__ out, int nNodes)
{
    int t = blockIdx.x * blockDim.x + threadIdx.x;
    int w = t >> 5, lane = t & 31;
    if (w >= nNodes) return;
    int deg = cnt[w];
    if (deg > CAP) deg = CAP;
    const int* sl = slot + (size_t)w * CAP;
    float4 a0 = make_float4(0.f, 0.f, 0.f, 0.f), a1 = a0, a2 = a0, a3 = a0;
    int j = 0;
    for (; j + 8 <= deg; j += 8) {
        int4 i0 = *reinterpret_cast<const int4*>(sl + j);
        int4 i1 = *reinterpret_cast<const int4*>(sl + j + 4);
        float4 v0 = reinterpret_cast<const float4*>(feat + (size_t)i0.x * D)[lane];
        float4 v1 = reinterpret_cast<const float4*>(feat + (size_t)i0.y * D)[lane];
        float4 v2 = reinterpret_cast<const float4*>(feat + (size_t)i0.z * D)[lane];
        float4 v3 = reinterpret_cast<const float4*>(feat + (size_t)i0.w * D)[lane];
        float4 v4 = reinterpret_cast<const float4*>(feat + (size_t)i1.x * D)[lane];
        float4 v5 = reinterpret_cast<const float4*>(feat + (size_t)i1.y * D)[lane];
        float4 v6 = reinterpret_cast<const float4*>(feat + (size_t)i1.z * D)[lane];
        float4 v7 = reinterpret_cast<const float4*>(feat + (size_t)i1.w * D)[lane];
        a0.x += v0.x; a0.y += v0.y; a0.z += v0.z; a0.w += v0.w;
        a1.x += v1.x; a1.y += v1.y; a1.z += v1.z; a1.w += v1.w;
        a2.x += v2.x; a2.y += v2.y; a2.z += v2.z; a2.w += v2.w;
        a3.x += v3.x; a3.y += v3.y; a3.z += v3.z; a3.w += v3.w;
        a0.x += v4.x; a0.y += v4.y; a0.z += v4.z; a0.w += v4.w;
        a1.x += v5.x; a1.y += v5.y; a1.z += v5.z; a1.w += v5.w;
        a2.x += v6.x; a2.y += v6.y; a2.z += v6.z; a2.w += v6.w;
        a3.x += v7.x; a3.y += v7.y; a3.z += v7.z; a3.w += v7.w;
    }
    if (j + 4 <= deg) {
        int4 i0 = *reinterpret_cast<const int4*>(sl + j);
        float4 v0 = reinterpret_cast<const float4*>(feat + (size_t)i0.x * D)[lane];
        float4 v1 = reinterpret_cast<const float4*>(feat + (size_t)i0.y * D)[lane];
        float4 v2 = reinterpret_cast<const float4*>(feat + (size_t)i0.z * D)[lane];
        float4 v3 = reinterpret_cast<const float4*>(feat + (size_t)i0.w * D)[lane];
        a0.x += v0.x; a0.y += v0.y; a0.z += v0.z; a0.w += v0.w;
        a1.x += v1.x; a1.y += v1.y; a1.z += v1.z; a1.w += v1.w;
        a2.x += v2.x; a2.y += v2.y; a2.z += v2.z; a2.w += v2.w;
        a3.x += v3.x; a3.y += v3.y; a3.z += v3.z; a3.w += v3.w;
        j += 4;
    }
    for (; j < deg; j++) {
        float4 v = reinterpret_cast<const float4*>(feat + (size_t)sl[j] * D)[lane];
        a0.x += v.x; a0.y += v.y; a0.z += v.z; a0.w += v.w;
    }
    float4 r;
    r.x = (a0.x + a1.x) + (a2.x + a3.x);
    r.y = (a0.y + a1.y) + (a2.y + a3.y);
    r.z = (a0.z + a1.z) + (a2.z + a3.z);
    r.w = (a0.w + a1.w) + (a2.w + a3.w);
    reinterpret_cast<float4*>(out + (size_t)w * D)[lane] = r;
}

// ---------------------------------------------------------------------------
// fp16 split helpers + one-time W conversion (Wm + 2 combined Wc)
// ---------------------------------------------------------------------------
__device__ __forceinline__ unsigned pack_split(float x0, float x1, unsigned& lo)
{
    __half h0 = __float2half_rn(x0), h1 = __float2half_rn(x1);
    __half l0 = __float2half_rn(x0 - __half2float(h0));
    __half l1 = __float2half_rn(x1 - __half2float(h1));
    __half2 lv = __halves2half2(l0, l1);
    __half2 hv = __halves2half2(h0, h1);
    lo = *reinterpret_cast<unsigned*>(&lv);
    return *reinterpret_cast<unsigned*>(&hv);
}

__global__ void convert_w_k(const float* __restrict__ Wm)
{
    int m = blockIdx.y;
    const float* W = (m == 0) ? Wm : (g_Wc + (m - 1) * 16384);
    unsigned* dhi = g_Whi + m * WS_WORDS;
    unsigned* dlo = g_Wlo + m * WS_WORDS;
    int e = blockIdx.x * blockDim.x + threadIdx.x;
    int kw = e >> 7, n = e & 127;
    float w0 = W[(size_t)(2 * kw)     * 128 + n];
    float w1 = W[(size_t)(2 * kw + 1) * 128 + n];
    unsigned lo;
    unsigned hi = pack_split(w0, w1, lo);
    dhi[kw * WS_STRIDE + n] = hi;
    dlo[kw * WS_STRIDE + n] = lo;
}

// ---------------------------------------------------------------------------
// fp16x3 tensor GEMM: y[M,128] = epi( (A (+A2)) @ W + bias (+res) (+deg*dvec) )
// ---------------------------------------------------------------------------
#define AS_STRIDE 68
#define AS_WORDS  (64 * AS_STRIDE)
#define SMEM_BYTES ((2 * AS_WORDS + 2 * WS_WORDS) * 4)

__device__ __forceinline__ void mma16(float c[4], const unsigned a[4], const unsigned b[2])
{
    asm volatile(
        "mma.sync.aligned.m16n8k16.row.col.f32.f16.f16.f32 "
        "{%0,%1,%2,%3}, {%4,%5,%6,%7}, {%8,%9}, {%0,%1,%2,%3};"
        : "+f"(c[0]), "+f"(c[1]), "+f"(c[2]), "+f"(c[3])
        : "r"(a[0]), "r"(a[1]), "r"(a[2]), "r"(a[3]), "r"(b[0]), "r"(b[1]));
}

template<bool RELU, bool HAS_IN2, bool HAS_RES, bool HAS_DEG>
__global__ __launch_bounds__(256, 2)
void gemm128_h3(const float* __restrict__ A, const float* __restrict__ A2,
                const unsigned* __restrict__ Whi, const unsigned* __restrict__ Wlo,
                const float* __restrict__ bias,
                const float* __restrict__ res,
                const int* __restrict__ degp, const float* __restrict__ dvec,
                float* __restrict__ out, int M)
{
    extern __shared__ unsigned sm[];
    unsigned* As_hi = sm;
    unsigned* As_lo = sm + AS_WORDS;
    unsigned* Ws_hi = sm + 2 * AS_WORDS;
    unsigned* Ws_lo = sm + 2 * AS_WORDS + WS_WORDS;

    const int tid    = threadIdx.x;
    const int lane   = tid & 31;
    const int wid    = tid >> 5;
    const int warp_m = wid & 1;
    const int warp_n = wid >> 1;
    const int grp    = lane >> 2;
    const int tig    = lane & 3;
    const int row0   = blockIdx.x * 64;

    {
        unsigned shi = (unsigned)__cvta_generic_to_shared(Ws_hi);
        unsigned slo = (unsigned)__cvta_generic_to_shared(Ws_lo);
        #pragma unroll
        for (int i = 0; i < 8; i++) {
            int off = (tid + i * 256) * 16;
            asm volatile("cp.async.cg.shared.global [%0], [%1], 16;"
                         :: "r"(shi + off), "l"((const char*)Whi + off));
            asm volatile("cp.async.cg.shared.global [%0], [%1], 16;"
                         :: "r"(slo + off), "l"((const char*)Wlo + off));
        }
        if (tid < 128) {
            int off = 8 * 4096 + tid * 16;
            asm volatile("cp.async.cg.shared.global [%0], [%1], 16;"
                         :: "r"(shi + off), "l"((const char*)Whi + off));
            asm volatile("cp.async.cg.shared.global [%0], [%1], 16;"
                         :: "r"(slo + off), "l"((const char*)Wlo + off));
        }
        asm volatile("cp.async.commit_group;");
    }

    #pragma unroll
    for (int h = 0; h < 8; h++) {
        int e = tid * 4 + h * 1024;
        int r = e >> 7, k = e & 127;
        int grow = row0 + r;
        float4 v = make_float4(0.f, 0.f, 0.f, 0.f);
        if (grow < M) {
            v = *reinterpret_cast<const float4*>(A + (size_t)grow * 128 + k);
            if (HAS_IN2) {
                float4 u = *reinterpret_cast<const float4*>(A2 + (size_t)grow * 128 + k);
                v.x += u.x; v.y += u.y; v.z += u.z; v.w += u.w;
            }
        }
        unsigned lo0, lo1;
        unsigned hi0 = pack_split(v.x, v.y, lo0);
        unsigned hi1 = pack_split(v.z, v.w, lo1);
        int base = r * AS_STRIDE + (k >> 1);
        *reinterpret_cast<uint2*>(&As_hi[base]) = make_uint2(hi0, hi1);
        *reinterpret_cast<uint2*>(&As_lo[base]) = make_uint2(lo0, lo1);
    }

    asm volatile("cp.async.wait_group 0;");
    __syncthreads();

    float acc[2][4][4];
    #pragma unroll
    for (int i = 0; i < 2; i++)
        #pragma unroll
        for (int j = 0; j < 4; j++)
            #pragma unroll
            for (int c = 0; c < 4; c++) acc[i][j][c] = 0.f;

    #pragma unroll
    for (int kw0 = 0; kw0 < 64; kw0 += 8) {
        unsigned ah[2][4], al[2][4];
        #pragma unroll
        for (int i = 0; i < 2; i++) {
            int r = warp_m * 32 + i * 16 + grp;
            int b0 = r * AS_STRIDE + kw0 + tig;
            int b8 = (r + 8) * AS_STRIDE + kw0 + tig;
            ah[i][0] = As_hi[b0];     al[i][0] = As_lo[b0];
            ah[i][1] = As_hi[b8];     al[i][1] = As_lo[b8];
            ah[i][2] = As_hi[b0 + 4]; al[i][2] = As_lo[b0 + 4];
            ah[i][3] = As_hi[b8 + 4]; al[i][3] = As_lo[b8 + 4];
        }
        unsigned bh[4][2], bl[4][2];
        #pragma unroll
        for (int j = 0; j < 4; j++) {
            int n = warp_n * 32 + j * 8 + grp;
            int t0 = (kw0 + tig) * WS_STRIDE + n;
            int t4 = (kw0 + tig + 4) * WS_STRIDE + n;
            bh[j][0] = Ws_hi[t0];  bl[j][0] = Ws_lo[t0];
            bh[j][1] = Ws_hi[t4];  bl[j][1] = Ws_lo[t4];
        }
        #pragma unroll
        for (int i = 0; i < 2; i++)
            #pragma unroll
            for (int j = 0; j < 4; j++) {
                mma16(acc[i][j], ah[i], bh[j]);
                mma16(acc[i][j], ah[i], bl[j]);
                mma16(acc[i][j], al[i], bh[j]);
            }
    }

    #pragma unroll
    for (int j = 0; j < 4; j++) {
        int col = warp_n * 32 + j * 8 + tig * 2;
        float2 bv = *reinterpret_cast<const float2*>(bias + col);
        float2 dv = make_float2(0.f, 0.f);
        if (HAS_DEG) dv = *reinterpret_cast<const float2*>(dvec + col);
        #pragma unroll
        for (int i = 0; i < 2; i++) {
            int rbase = row0 + warp_m * 32 + i * 16 + grp;
            #pragma unroll
            for (int half = 0; half < 2; half++) {
                int r = rbase + half * 8;
                if (r >= M) continue;
                float2 v;
                v.x = acc[i][j][half * 2 + 0] + bv.x;
                v.y = acc[i][j][half * 2 + 1] + bv.y;
                if (HAS_DEG) {
                    float dg = (float)degp[r];
                    v.x += dg * dv.x; v.y += dg * dv.y;
                }
                if (HAS_RES) {
                    float2 rr = *reinterpret_cast<const float2*>(res + (size_t)r * 128 + col);
                    v.x += rr.x; v.y += rr.y;
                }
                if (RELU) { v.x = fmaxf(v.x, 0.f); v.y = fmaxf(v.y, 0.f); }
                *reinterpret_cast<float2*>(out + (size_t)r * 128 + col) = v;
            }
        }
    }
}

// ---------------------------------------------------------------------------

extern "C" void kernel_launch(void* const* d_in, const int* in_sizes, int n_in,
                              void* d_out, int out_size)
{
    const float* x     = (const float*)d_in[0];
    const float* Wm    = (const float*)d_in[1];
    const float* bm    = (const float*)d_in[2];
    const float* Wn2s0 = (const float*)d_in[3];
    const float* bn2s0 = (const float*)d_in[4];
    const float* Ws2n0 = (const float*)d_in[5];
    const float* bs2n0 = (const float*)d_in[6];
    const float* Wn2s1 = (const float*)d_in[7];
    const float* bn2s1 = (const float*)d_in[8];
    const float* Ws2n1 = (const float*)d_in[9];
    const float* bs2n1 = (const float*)d_in[10];
    const int* nei = (const int*)d_in[11];
    const int* r0  = (const int*)d_in[12];
    const int* c0  = (const int*)d_in[13];
    const int* r1  = (const int*)d_in[14];
    const int* c1  = (const int*)d_in[15];
    float* out = (float*)d_out;

    float *agg, *h, *h1, *sub, *dvec;
    unsigned *whi, *wlo;
    int *cnt, *slNE, *slS0, *slS1, *slN0, *slN1;
    cudaGetSymbolAddress((void**)&agg,  g_agg);
    cudaGetSymbolAddress((void**)&h,    g_h);
    cudaGetSymbolAddress((void**)&h1,   g_h1);
    cudaGetSymbolAddress((void**)&sub,  g_sub);
    cudaGetSymbolAddress((void**)&dvec, g_dvec);
    cudaGetSymbolAddress((void**)&whi,  g_Whi);
    cudaGetSymbolAddress((void**)&wlo,  g_Wlo);
    cudaGetSymbolAddress((void**)&cnt,  g_cnt);
    cudaGetSymbolAddress((void**)&slNE, g_slotNE);
    cudaGetSymbolAddress((void**)&slS0, g_slotS2N0);
    cudaGetSymbolAddress((void**)&slS1, g_slotS2N1);
    cudaGetSymbolAddress((void**)&slN0, g_slotN2S0);
    cudaGetSymbolAddress((void**)&slN1, g_slotN2S1);

    cudaFuncSetAttribute(gemm128_h3<true,  true,  false, false>,
                         cudaFuncAttributeMaxDynamicSharedMemorySize, SMEM_BYTES);
    cudaFuncSetAttribute(gemm128_h3<false, false, true,  true>,
                         cudaFuncAttributeMaxDynamicSharedMemorySize, SMEM_BYTES);

    const int GB_N = (NN + 63) / 64;
    const int RB_N = (NN * 32 + 255) / 256;
    const int RB_S = (NS * 32 + 255) / 256;
    const int FB   = (NE + 4 * 256 - 1) / (4 * 256);   // 586 blocks, 4 edges/thread

    // Prep: cnt memset -> merged fill; combined weights -> fp16 splits
    cudaMemsetAsync(cnt, 0, (3 * NN + 2 * NS) * sizeof(int));
    fill_all_k<<<dim3(FB, 5), 256>>>(nei, r0, c0, r1, c1);
    wcdvec_k<<<dim3(129, 2), 128>>>(Wn2s0, Ws2n0, bn2s0, Wn2s1, Ws2n1, bn2s1);
    convert_w_k<<<dim3(32, 3), 256>>>(Wm);

    // message_neighbor: h = relu((x + segsum(x)) @ Wm + bm)
    reduce_k<<<RB_N, 256>>>(x, cnt + C_NE, slNE, agg, NN);
    gemm128_h3<true, true, false, false><<<GB_N, 256, SMEM_BYTES>>>(
        x, agg, whi + 0 * WS_WORDS, wlo + 0 * WS_WORDS, bm, nullptr,
        nullptr, nullptr, h, NN);

    // level 0: t0 = S0 h ; u0 = S0^T t0 ; h1 = h + u0@Wc0 + deg0*dvec0 + bs2n0
    reduce_k<<<RB_S, 256>>>(h, cnt + C_N2S0, slN0, sub, NS);
    reduce_k<<<RB_N, 256>>>(sub, cnt + C_S2N0, slS0, agg, NN);
    gemm128_h3<false, false, true, true><<<GB_N, 256, SMEM_BYTES>>>(
        agg, nullptr, whi + 1 * WS_WORDS, wlo + 1 * WS_WORDS, bs2n0, h,
        cnt + C_S2N0, dvec + 0, h1, NN);

    // level 1
    reduce_k<<<RB_S, 256>>>(h1, cnt + C_N2S1, slN1, sub, NS);
    reduce_k<<<RB_N, 256>>>(sub, cnt + C_S2N1, slS1, agg, NN);
    gemm128_h3<false, false, true, true><<<GB_N, 256, SMEM_BYTES>>>(
        agg, nullptr, whi + 2 * WS_WORDS, wlo + 2 * WS_WORDS, bs2n1, h1,
        cnt + C_S2N1, dvec + 128, out, NN);
}

// round 13
// speedup vs baseline: 1.1144x; 1.1144x over previous
#include <cuda_runtime.h>
#include <cuda_fp16.h>
#include <cuda_bf16.h>

#define D 128
#define NN 50000
#define NS 20000
#define NE 600000
#define ES 120000
#define CAP 64

// Feature buffers
__device__ float g_agg [(size_t)NN * D];
__device__ float g_h   [(size_t)NN * D];
__device__ float g_h1  [(size_t)NN * D];
__device__ float g_sub [(size_t)NS * D];

// Combined weights Wc = Wn2s @ Ws2n (fp32, per level) + deg-bias vectors
__device__ float g_Wc[2 * 128 * 128];
__device__ float g_dvec[2 * 128];

// Bucket CSR scratch: cnt contiguous (one memset), slots per phase
#define C_NE   0
#define C_S2N0 (NN)
#define C_S2N1 (2 * NN)
#define C_N2S0 (3 * NN)
#define C_N2S1 (3 * NN + NS)
__device__ int g_cnt[3 * NN + 2 * NS];
__device__ int g_slotNE  [(size_t)NN * CAP];
__device__ int g_slotS2N0[(size_t)NN * CAP];
__device__ int g_slotS2N1[(size_t)NN * CAP];
__device__ int g_slotN2S0[(size_t)NS * CAP];
__device__ int g_slotN2S1[(size_t)NS * CAP];

// Precomputed fp16 hi/lo W splits (smem layout): 0=Wm, 1=Wc0, 2=Wc1
#define WS_STRIDE 136
#define WS_WORDS  (64 * WS_STRIDE)
__device__ unsigned g_Whi[3 * WS_WORDS];
__device__ unsigned g_Wlo[3 * WS_WORDS];

// ---------------------------------------------------------------------------
// Prep: combined weights Wc = A@B and dvec = b@B, one kernel
// ---------------------------------------------------------------------------
__global__ void wcdvec_k(const float* __restrict__ A0, const float* __restrict__ B0,
                         const float* __restrict__ b0,
                         const float* __restrict__ A1, const float* __restrict__ B1,
                         const float* __restrict__ b1)
{
    __shared__ float a[128];
    int lvl = blockIdx.y;
    const float* A = lvl ? A1 : A0;
    const float* B = lvl ? B1 : B0;
    const float* b = lvl ? b1 : b0;
    int i = blockIdx.x, j = threadIdx.x;
    a[j] = (i < 128) ? A[i * 128 + j] : b[j];
    __syncthreads();
    float acc = 0.f;
    #pragma unroll 8
    for (int k = 0; k < 128; k++) acc += a[k] * B[k * 128 + j];
    if (i < 128) g_Wc[lvl * 16384 + i * 128 + j] = acc;
    else         g_dvec[lvl * 128 + j] = acc;
}

// ---------------------------------------------------------------------------
// Merged bucket fill: one launch, blockIdx.y = phase (0=NE, 1..4=ES), 1 edge/thread
// ---------------------------------------------------------------------------
__global__ void fill_all_k(const int* __restrict__ nei,
                           const int* __restrict__ r0, const int* __restrict__ c0,
                           const int* __restrict__ r1, const int* __restrict__ c1)
{
    int e = blockIdx.x * blockDim.x + threadIdx.x;
    int ph = blockIdx.y;
    const int* gi; const int* si; int cbase; int* slot; int n;
    switch (ph) {
        case 0:  gi = nei; si = nei + NE; cbase = C_NE;   slot = g_slotNE;   n = NE; break;
        case 1:  gi = r0;  si = c0;       cbase = C_N2S0; slot = g_slotN2S0; n = ES; break;
        case 2:  gi = c0;  si = r0;       cbase = C_S2N0; slot = g_slotS2N0; n = ES; break;
        case 3:  gi = r1;  si = c1;       cbase = C_N2S1; slot = g_slotN2S1; n = ES; break;
        default: gi = c1;  si = r1;       cbase = C_S2N1; slot = g_slotS2N1; n = ES; break;
    }
    if (e >= n) return;
    int s = si[e];
    int p = atomicAdd(&g_cnt[cbase + s], 1);
    if (p < CAP) slot[(size_t)s * CAP + p] = gi[e];
}

// ---------------------------------------------------------------------------
// Warp-per-node gather reduce (R10-proven MLP-4, 40 regs)
// ---------------------------------------------------------------------------
__global__ void reduce_k(const float* __restrict__ feat,
                         const int* __restrict__ cnt, const int* __restrict__ slot,
                         float* __restrict__ out, int nNodes)
{
    int t = blockIdx.x * blockDim.x + threadIdx.x;
    int w = t >> 5, lane = t & 31;
    if (w >= nNodes) return;
    int deg = cnt[w];
    if (deg > CAP) deg = CAP;
    const int* sl = slot + (size_t)w * CAP;
    float4 a0 = make_float4(0.f, 0.f, 0.f, 0.f), a1 = a0, a2 = a0, a3 = a0;
    int j = 0;
    for (; j + 4 <= deg; j += 4) {
        int s0 = sl[j], s1 = sl[j + 1], s2 = sl[j + 2], s3 = sl[j + 3];
        float4 v0 = reinterpret_cast<const float4*>(feat + (size_t)s0 * D)[lane];
        float4 v1 = reinterpret_cast<const float4*>(feat + (size_t)s1 * D)[lane];
        float4 v2 = reinterpret_cast<const float4*>(feat + (size_t)s2 * D)[lane];
        float4 v3 = reinterpret_cast<const float4*>(feat + (size_t)s3 * D)[lane];
        a0.x += v0.x; a0.y += v0.y; a0.z += v0.z; a0.w += v0.w;
        a1.x += v1.x; a1.y += v1.y; a1.z += v1.z; a1.w += v1.w;
        a2.x += v2.x; a2.y += v2.y; a2.z += v2.z; a2.w += v2.w;
        a3.x += v3.x; a3.y += v3.y; a3.z += v3.z; a3.w += v3.w;
    }
    for (; j < deg; j++) {
        float4 v = reinterpret_cast<const float4*>(feat + (size_t)sl[j] * D)[lane];
        a0.x += v.x; a0.y += v.y; a0.z += v.z; a0.w += v.w;
    }
    float4 r;
    r.x = (a0.x + a1.x) + (a2.x + a3.x);
    r.y = (a0.y + a1.y) + (a2.y + a3.y);
    r.z = (a0.z + a1.z) + (a2.z + a3.z);
    r.w = (a0.w + a1.w) + (a2.w + a3.w);
    reinterpret_cast<float4*>(out + (size_t)w * D)[lane] = r;
}

// ---------------------------------------------------------------------------
// fp16 split helpers + one-time W conversion (Wm + 2 combined Wc)
// ---------------------------------------------------------------------------
__device__ __forceinline__ unsigned pack_split(float x0, float x1, unsigned& lo)
{
    __half h0 = __float2half_rn(x0), h1 = __float2half_rn(x1);
    __half l0 = __float2half_rn(x0 - __half2float(h0));
    __half l1 = __float2half_rn(x1 - __half2float(h1));
    __half2 lv = __halves2half2(l0, l1);
    __half2 hv = __halves2half2(h0, h1);
    lo = *reinterpret_cast<unsigned*>(&lv);
    return *reinterpret_cast<unsigned*>(&hv);
}

__global__ void convert_w_k(const float* __restrict__ Wm)
{
    int m = blockIdx.y;
    const float* W = (m == 0) ? Wm : (g_Wc + (m - 1) * 16384);
    unsigned* dhi = g_Whi + m * WS_WORDS;
    unsigned* dlo = g_Wlo + m * WS_WORDS;
    int e = blockIdx.x * blockDim.x + threadIdx.x;
    int kw = e >> 7, n = e & 127;
    float w0 = W[(size_t)(2 * kw)     * 128 + n];
    float w1 = W[(size_t)(2 * kw + 1) * 128 + n];
    unsigned lo;
    unsigned hi = pack_split(w0, w1, lo);
    dhi[kw * WS_STRIDE + n] = hi;
    dlo[kw * WS_STRIDE + n] = lo;
}

// ---------------------------------------------------------------------------
// fp16x3 tensor GEMM: y[M,128] = epi( (A (+A2)) @ W + bias (+res) (+deg*dvec) )
// ---------------------------------------------------------------------------
#define AS_STRIDE 68
#define AS_WORDS  (64 * AS_STRIDE)
#define SMEM_BYTES ((2 * AS_WORDS + 2 * WS_WORDS) * 4)

__device__ __forceinline__ void mma16(float c[4], const unsigned a[4], const unsigned b[2])
{
    asm volatile(
        "mma.sync.aligned.m16n8k16.row.col.f32.f16.f16.f32 "
        "{%0,%1,%2,%3}, {%4,%5,%6,%7}, {%8,%9}, {%0,%1,%2,%3};"
        : "+f"(c[0]), "+f"(c[1]), "+f"(c[2]), "+f"(c[3])
        : "r"(a[0]), "r"(a[1]), "r"(a[2]), "r"(a[3]), "r"(b[0]), "r"(b[1]));
}

template<bool RELU, bool HAS_IN2, bool HAS_RES, bool HAS_DEG>
__global__ __launch_bounds__(256, 2)
void gemm128_h3(const float* __restrict__ A, const float* __restrict__ A2,
                const unsigned* __restrict__ Whi, const unsigned* __restrict__ Wlo,
                const float* __restrict__ bias,
                const float* __restrict__ res,
                const int* __restrict__ degp, const float* __restrict__ dvec,
                float* __restrict__ out, int M)
{
    extern __shared__ unsigned sm[];
    unsigned* As_hi = sm;
    unsigned* As_lo = sm + AS_WORDS;
    unsigned* Ws_hi = sm + 2 * AS_WORDS;
    unsigned* Ws_lo = sm + 2 * AS_WORDS + WS_WORDS;

    const int tid    = threadIdx.x;
    const int lane   = tid & 31;
    const int wid    = tid >> 5;
    const int warp_m = wid & 1;
    const int warp_n = wid >> 1;
    const int grp    = lane >> 2;
    const int tig    = lane & 3;
    const int row0   = blockIdx.x * 64;

    {
        unsigned shi = (unsigned)__cvta_generic_to_shared(Ws_hi);
        unsigned slo = (unsigned)__cvta_generic_to_shared(Ws_lo);
        #pragma unroll
        for (int i = 0; i < 8; i++) {
            int off = (tid + i * 256) * 16;
            asm volatile("cp.async.cg.shared.global [%0], [%1], 16;"
                         :: "r"(shi + off), "l"((const char*)Whi + off));
            asm volatile("cp.async.cg.shared.global [%0], [%1], 16;"
                         :: "r"(slo + off), "l"((const char*)Wlo + off));
        }
        if (tid < 128) {
            int off = 8 * 4096 + tid * 16;
            asm volatile("cp.async.cg.shared.global [%0], [%1], 16;"
                         :: "r"(shi + off), "l"((const char*)Whi + off));
            asm volatile("cp.async.cg.shared.global [%0], [%1], 16;"
                         :: "r"(slo + off), "l"((const char*)Wlo + off));
        }
        asm volatile("cp.async.commit_group;");
    }

    #pragma unroll
    for (int h = 0; h < 8; h++) {
        int e = tid * 4 + h * 1024;
        int r = e >> 7, k = e & 127;
        int grow = row0 + r;
        float4 v = make_float4(0.f, 0.f, 0.f, 0.f);
        if (grow < M) {
            v = *reinterpret_cast<const float4*>(A + (size_t)grow * 128 + k);
            if (HAS_IN2) {
                float4 u = *reinterpret_cast<const float4*>(A2 + (size_t)grow * 128 + k);
                v.x += u.x; v.y += u.y; v.z += u.z; v.w += u.w;
            }
        }
        unsigned lo0, lo1;
        unsigned hi0 = pack_split(v.x, v.y, lo0);
        unsigned hi1 = pack_split(v.z, v.w, lo1);
        int base = r * AS_STRIDE + (k >> 1);
        *reinterpret_cast<uint2*>(&As_hi[base]) = make_uint2(hi0, hi1);
        *reinterpret_cast<uint2*>(&As_lo[base]) = make_uint2(lo0, lo1);
    }

    asm volatile("cp.async.wait_group 0;");
    __syncthreads();

    float acc[2][4][4];
    #pragma unroll
    for (int i = 0; i < 2; i++)
        #pragma unroll
        for (int j = 0; j < 4; j++)
            #pragma unroll
            for (int c = 0; c < 4; c++) acc[i][j][c] = 0.f;

    #pragma unroll
    for (int kw0 = 0; kw0 < 64; kw0 += 8) {
        unsigned ah[2][4], al[2][4];
        #pragma unroll
        for (int i = 0; i < 2; i++) {
            int r = warp_m * 32 + i * 16 + grp;
            int b0 = r * AS_STRIDE + kw0 + tig;
            int b8 = (r + 8) * AS_STRIDE + kw0 + tig;
            ah[i][0] = As_hi[b0];     al[i][0] = As_lo[b0];
            ah[i][1] = As_hi[b8];     al[i][1] = As_lo[b8];
            ah[i][2] = As_hi[b0 + 4]; al[i][2] = As_lo[b0 + 4];
            ah[i][3] = As_hi[b8 + 4]; al[i][3] = As_lo[b8 + 4];
        }
        unsigned bh[4][2], bl[4][2];
        #pragma unroll
        for (int j = 0; j < 4; j++) {
            int n = warp_n * 32 + j * 8 + grp;
            int t0 = (kw0 + tig) * WS_STRIDE + n;
            int t4 = (kw0 + tig + 4) * WS_STRIDE + n;
            bh[j][0] = Ws_hi[t0];  bl[j][0] = Ws_lo[t0];
            bh[j][1] = Ws_hi[t4];  bl[j][1] = Ws_lo[t4];
        }
        #pragma unroll
        for (int i = 0; i < 2; i++)
            #pragma unroll
            for (int j = 0; j < 4; j++) {
                mma16(acc[i][j], ah[i], bh[j]);
                mma16(acc[i][j], ah[i], bl[j]);
                mma16(acc[i][j], al[i], bh[j]);
            }
    }

    #pragma unroll
    for (int j = 0; j < 4; j++) {
        int col = warp_n * 32 + j * 8 + tig * 2;
        float2 bv = *reinterpret_cast<const float2*>(bias + col);
        float2 dv = make_float2(0.f, 0.f);
        if (HAS_DEG) dv = *reinterpret_cast<const float2*>(dvec + col);
        #pragma unroll
        for (int i = 0; i < 2; i++) {
            int rbase = row0 + warp_m * 32 + i * 16 + grp;
            #pragma unroll
            for (int half = 0; half < 2; half++) {
                int r = rbase + half * 8;
                if (r >= M) continue;
                float2 v;
                v.x = acc[i][j][half * 2 + 0] + bv.x;
                v.y = acc[i][j][half * 2 + 1] + bv.y;
                if (HAS_DEG) {
                    float dg = (float)degp[r];
                    v.x += dg * dv.x; v.y += dg * dv.y;
                }
                if (HAS_RES) {
                    float2 rr = *reinterpret_cast<const float2*>(res + (size_t)r * 128 + col);
                    v.x += rr.x; v.y += rr.y;
                }
                if (RELU) { v.x = fmaxf(v.x, 0.f); v.y = fmaxf(v.y, 0.f); }
                *reinterpret_cast<float2*>(out + (size_t)r * 128 + col) = v;
            }
        }
    }
}

// ---------------------------------------------------------------------------

extern "C" void kernel_launch(void* const* d_in, const int* in_sizes, int n_in,
                              void* d_out, int out_size)
{
    const float* x     = (const float*)d_in[0];
    const float* Wm    = (const float*)d_in[1];
    const float* bm    = (const float*)d_in[2];
    const float* Wn2s0 = (const float*)d_in[3];
    const float* bn2s0 = (const float*)d_in[4];
    const float* Ws2n0 = (const float*)d_in[5];
    const float* bs2n0 = (const float*)d_in[6];
    const float* Wn2s1 = (const float*)d_in[7];
    const float* bn2s1 = (const float*)d_in[8];
    const float* Ws2n1 = (const float*)d_in[9];
    const float* bs2n1 = (const float*)d_in[10];
    const int* nei = (const int*)d_in[11];
    const int* r0  = (const int*)d_in[12];
    const int* c0  = (const int*)d_in[13];
    const int* r1  = (const int*)d_in[14];
    const int* c1  = (const int*)d_in[15];
    float* out = (float*)d_out;

    float *agg, *h, *h1, *sub, *dvec;
    unsigned *whi, *wlo;
    int *cnt, *slNE, *slS0, *slS1, *slN0, *slN1;
    cudaGetSymbolAddress((void**)&agg,  g_agg);
    cudaGetSymbolAddress((void**)&h,    g_h);
    cudaGetSymbolAddress((void**)&h1,   g_h1);
    cudaGetSymbolAddress((void**)&sub,  g_sub);
    cudaGetSymbolAddress((void**)&dvec, g_dvec);
    cudaGetSymbolAddress((void**)&whi,  g_Whi);
    cudaGetSymbolAddress((void**)&wlo,  g_Wlo);
    cudaGetSymbolAddress((void**)&cnt,  g_cnt);
    cudaGetSymbolAddress((void**)&slNE, g_slotNE);
    cudaGetSymbolAddress((void**)&slS0, g_slotS2N0);
    cudaGetSymbolAddress((void**)&slS1, g_slotS2N1);
    cudaGetSymbolAddress((void**)&slN0, g_slotN2S0);
    cudaGetSymbolAddress((void**)&slN1, g_slotN2S1);

    cudaFuncSetAttribute(gemm128_h3<true,  true,  false, false>,
                         cudaFuncAttributeMaxDynamicSharedMemorySize, SMEM_BYTES);
    cudaFuncSetAttribute(gemm128_h3<false, false, true,  true>,
                         cudaFuncAttributeMaxDynamicSharedMemorySize, SMEM_BYTES);

    const int GB_N = (NN + 63) / 64;
    const int RB_N = (NN * 32 + 255) / 256;
    const int RB_S = (NS * 32 + 255) / 256;
    const int FB   = (NE + 255) / 256;   // 2344; ES phases early-exit

    // Prep: cnt memset -> merged fill (5 phases co-resident); weights
    cudaMemsetAsync(cnt, 0, (3 * NN + 2 * NS) * sizeof(int));
    fill_all_k<<<dim3(FB, 5), 256>>>(nei, r0, c0, r1, c1);
    wcdvec_k<<<dim3(129, 2), 128>>>(Wn2s0, Ws2n0, bn2s0, Wn2s1, Ws2n1, bn2s1);
    convert_w_k<<<dim3(32, 3), 256>>>(Wm);

    // message_neighbor: h = relu((x + segsum(x)) @ Wm + bm)
    reduce_k<<<RB_N, 256>>>(x, cnt + C_NE, slNE, agg, NN);
    gemm128_h3<true, true, false, false><<<GB_N, 256, SMEM_BYTES>>>(
        x, agg, whi + 0 * WS_WORDS, wlo + 0 * WS_WORDS, bm, nullptr,
        nullptr, nullptr, h, NN);

    // level 0: t0 = S0 h ; u0 = S0^T t0 ; h1 = h + u0@Wc0 + deg0*dvec0 + bs2n0
    reduce_k<<<RB_S, 256>>>(h, cnt + C_N2S0, slN0, sub, NS);
    reduce_k<<<RB_N, 256>>>(sub, cnt + C_S2N0, slS0, agg, NN);
    gemm128_h3<false, false, true, true><<<GB_N, 256, SMEM_BYTES>>>(
        agg, nullptr, whi + 1 * WS_WORDS, wlo + 1 * WS_WORDS, bs2n0, h,
        cnt + C_S2N0, dvec + 0, h1, NN);

    // level 1
    reduce_k<<<RB_S, 256>>>(h1, cnt + C_N2S1, slN1, sub, NS);
    reduce_k<<<RB_N, 256>>>(sub, cnt + C_S2N1, slS1, agg, NN);
    gemm128_h3<false, false, true, true><<<GB_N, 256, SMEM_BYTES>>>(
        agg, nullptr, whi + 2 * WS_WORDS, wlo + 2 * WS_WORDS, bs2n1, h1,
        cnt + C_S2N1, dvec + 128, out, NN);
}

// round 14
// speedup vs baseline: 1.1405x; 1.0234x over previous
#include <cuda_runtime.h>
#include <cuda_fp16.h>
#include <cuda_bf16.h>

#define D 128
#define NN 50000
#define NS 20000
#define NE 600000
#define ES 120000
#define CAP 64
#define NN_PAD 50048   // ceil(NN/64)*64

// Feature buffers (fp32)
__device__ float g_h   [(size_t)NN * D];
__device__ float g_h1  [(size_t)NN * D];
__device__ float g_sub [(size_t)NS * D];

// GEMM A operand in pre-split fp16 hi/lo, padded GEMM smem layout:
// row w, kword kw (64 kwords + 4 pad) at [w*68 + kw]
#define AS_STRIDE 68
__device__ unsigned g_aggHi[(size_t)NN_PAD * AS_STRIDE];
__device__ unsigned g_aggLo[(size_t)NN_PAD * AS_STRIDE];

// Combined weights Wc = Wn2s @ Ws2n + deg-bias vectors
__device__ float g_Wc[2 * 128 * 128];
__device__ float g_dvec[2 * 128];

// Bucket CSR scratch
#define C_NE   0
#define C_S2N0 (NN)
#define C_S2N1 (2 * NN)
#define C_N2S0 (3 * NN)
#define C_N2S1 (3 * NN + NS)
__device__ int g_cnt[3 * NN + 2 * NS];
__device__ int g_slotNE  [(size_t)NN * CAP];
__device__ int g_slotS2N0[(size_t)NN * CAP];
__device__ int g_slotS2N1[(size_t)NN * CAP];
__device__ int g_slotN2S0[(size_t)NS * CAP];
__device__ int g_slotN2S1[(size_t)NS * CAP];

// Precomputed fp16 hi/lo W splits: 0=Wm, 1=Wc0, 2=Wc1
#define WS_STRIDE 136
#define WS_WORDS  (64 * WS_STRIDE)
__device__ unsigned g_Whi[3 * WS_WORDS];
__device__ unsigned g_Wlo[3 * WS_WORDS];

// ---------------------------------------------------------------------------
__device__ __forceinline__ unsigned pack_split(float x0, float x1, unsigned& lo)
{
    __half h0 = __float2half_rn(x0), h1 = __float2half_rn(x1);
    __half l0 = __float2half_rn(x0 - __half2float(h0));
    __half l1 = __float2half_rn(x1 - __half2float(h1));
    __half2 lv = __halves2half2(l0, l1);
    __half2 hv = __halves2half2(h0, h1);
    lo = *reinterpret_cast<unsigned*>(&lv);
    return *reinterpret_cast<unsigned*>(&hv);
}

// ---------------------------------------------------------------------------
// Prep: combined weights Wc = A@B and dvec = b@B
// ---------------------------------------------------------------------------
__global__ void wcdvec_k(const float* __restrict__ A0, const float* __restrict__ B0,
                         const float* __restrict__ b0,
                         const float* __restrict__ A1, const float* __restrict__ B1,
                         const float* __restrict__ b1)
{
    __shared__ float a[128];
    int lvl = blockIdx.y;
    const float* A = lvl ? A1 : A0;
    const float* B = lvl ? B1 : B0;
    const float* b = lvl ? b1 : b0;
    int i = blockIdx.x, j = threadIdx.x;
    a[j] = (i < 128) ? A[i * 128 + j] : b[j];
    __syncthreads();
    float acc = 0.f;
    #pragma unroll 8
    for (int k = 0; k < 128; k++) acc += a[k] * B[k * 128 + j];
    if (i < 128) g_Wc[lvl * 16384 + i * 128 + j] = acc;
    else         g_dvec[lvl * 128 + j] = acc;
}

__global__ void convert_w_k(const float* __restrict__ Wm)
{
    int m = blockIdx.y;
    const float* W = (m == 0) ? Wm : (g_Wc + (m - 1) * 16384);
    unsigned* dhi = g_Whi + m * WS_WORDS;
    unsigned* dlo = g_Wlo + m * WS_WORDS;
    int e = blockIdx.x * blockDim.x + threadIdx.x;
    int kw = e >> 7, n = e & 127;
    float w0 = W[(size_t)(2 * kw)     * 128 + n];
    float w1 = W[(size_t)(2 * kw + 1) * 128 + n];
    unsigned lo;
    unsigned hi = pack_split(w0, w1, lo);
    dhi[kw * WS_STRIDE + n] = hi;
    dlo[kw * WS_STRIDE + n] = lo;
}

// ---------------------------------------------------------------------------
// Merged bucket fill (5 phases in one launch)
// ---------------------------------------------------------------------------
__global__ void fill_all_k(const int* __restrict__ nei,
                           const int* __restrict__ r0, const int* __restrict__ c0,
                           const int* __restrict__ r1, const int* __restrict__ c1)
{
    int e = blockIdx.x * blockDim.x + threadIdx.x;
    int ph = blockIdx.y;
    const int* gi; const int* si; int cbase; int* slot; int n;
    switch (ph) {
        case 0:  gi = nei; si = nei + NE; cbase = C_NE;   slot = g_slotNE;   n = NE; break;
        case 1:  gi = r0;  si = c0;       cbase = C_N2S0; slot = g_slotN2S0; n = ES; break;
        case 2:  gi = c0;  si = r0;       cbase = C_S2N0; slot = g_slotS2N0; n = ES; break;
        case 3:  gi = r1;  si = c1;       cbase = C_N2S1; slot = g_slotN2S1; n = ES; break;
        default: gi = c1;  si = r1;       cbase = C_S2N1; slot = g_slotS2N1; n = ES; break;
    }
    if (e >= n) return;
    int s = si[e];
    int p = atomicAdd(&g_cnt[cbase + s], 1);
    if (p < CAP) slot[(size_t)s * CAP + p] = gi[e];
}

// ---------------------------------------------------------------------------
// Warp-per-node gather reduce -> fp32 out (for n2s phases)
// ---------------------------------------------------------------------------
__global__ void reduce_k(const float* __restrict__ feat,
                         const int* __restrict__ cnt, const int* __restrict__ slot,
                         float* __restrict__ out, int nNodes)
{
    int t = blockIdx.x * blockDim.x + threadIdx.x;
    int w = t >> 5, lane = t & 31;
    if (w >= nNodes) return;
    int deg = cnt[w];
    if (deg > CAP) deg = CAP;
    const int* sl = slot + (size_t)w * CAP;
    float4 a0 = make_float4(0.f, 0.f, 0.f, 0.f), a1 = a0, a2 = a0, a3 = a0;
    int j = 0;
    for (; j + 4 <= deg; j += 4) {
        int s0 = sl[j], s1 = sl[j + 1], s2 = sl[j + 2], s3 = sl[j + 3];
        float4 v0 = reinterpret_cast<const float4*>(feat + (size_t)s0 * D)[lane];
        float4 v1 = reinterpret_cast<const float4*>(feat + (size_t)s1 * D)[lane];
        float4 v2 = reinterpret_cast<const float4*>(feat + (size_t)s2 * D)[lane];
        float4 v3 = reinterpret_cast<const float4*>(feat + (size_t)s3 * D)[lane];
        a0.x += v0.x; a0.y += v0.y; a0.z += v0.z; a0.w += v0.w;
        a1.x += v1.x; a1.y += v1.y; a1.z += v1.z; a1.w += v1.w;
        a2.x += v2.x; a2.y += v2.y; a2.z += v2.z; a2.w += v2.w;
        a3.x += v3.x; a3.y += v3.y; a3.z += v3.z; a3.w += v3.w;
    }
    for (; j < deg; j++) {
        float4 v = reinterpret_cast<const float4*>(feat + (size_t)sl[j] * D)[lane];
        a0.x += v.x; a0.y += v.y; a0.z += v.z; a0.w += v.w;
    }
    float4 r;
    r.x = (a0.x + a1.x) + (a2.x + a3.x);
    r.y = (a0.y + a1.y) + (a2.y + a3.y);
    r.z = (a0.z + a1.z) + (a2.z + a3.z);
    r.w = (a0.w + a1.w) + (a2.w + a3.w);
    reinterpret_cast<float4*>(out + (size_t)w * D)[lane] = r;
}

// ---------------------------------------------------------------------------
// Gather reduce -> pre-split fp16 hi/lo in GEMM layout (for GEMM A feeds).
// HAS_BASE adds base[w] (the +x term of message_neighbor).
// lane holds kwords 2*lane, 2*lane+1 of row w.
// ---------------------------------------------------------------------------
template<bool HAS_BASE>
__global__ void reduce_hl_k(const float* __restrict__ feat,
                            const float* __restrict__ base,
                            const int* __restrict__ cnt, const int* __restrict__ slot,
                            int nNodes)
{
    int t = blockIdx.x * blockDim.x + threadIdx.x;
    int w = t >> 5, lane = t & 31;
    if (w >= nNodes) return;
    int deg = cnt[w];
    if (deg > CAP) deg = CAP;
    const int* sl = slot + (size_t)w * CAP;
    float4 a0 = make_float4(0.f, 0.f, 0.f, 0.f), a1 = a0, a2 = a0, a3 = a0;
    if (HAS_BASE)
        a0 = reinterpret_cast<const float4*>(base + (size_t)w * D)[lane];
    int j = 0;
    for (; j + 4 <= deg; j += 4) {
        int s0 = sl[j], s1 = sl[j + 1], s2 = sl[j + 2], s3 = sl[j + 3];
        float4 v0 = reinterpret_cast<const float4*>(feat + (size_t)s0 * D)[lane];
        float4 v1 = reinterpret_cast<const float4*>(feat + (size_t)s1 * D)[lane];
        float4 v2 = reinterpret_cast<const float4*>(feat + (size_t)s2 * D)[lane];
        float4 v3 = reinterpret_cast<const float4*>(feat + (size_t)s3 * D)[lane];
        a0.x += v0.x; a0.y += v0.y; a0.z += v0.z; a0.w += v0.w;
        a1.x += v1.x; a1.y += v1.y; a1.z += v1.z; a1.w += v1.w;
        a2.x += v2.x; a2.y += v2.y; a2.z += v2.z; a2.w += v2.w;
        a3.x += v3.x; a3.y += v3.y; a3.z += v3.z; a3.w += v3.w;
    }
    for (; j < deg; j++) {
        float4 v = reinterpret_cast<const float4*>(feat + (size_t)sl[j] * D)[lane];
        a0.x += v.x; a0.y += v.y; a0.z += v.z; a0.w += v.w;
    }
    float4 r;
    r.x = (a0.x + a1.x) + (a2.x + a3.x);
    r.y = (a0.y + a1.y) + (a2.y + a3.y);
    r.z = (a0.z + a1.z) + (a2.z + a3.z);
    r.w = (a0.w + a1.w) + (a2.w + a3.w);
    unsigned lo0, lo1;
    unsigned hi0 = pack_split(r.x, r.y, lo0);
    unsigned hi1 = pack_split(r.z, r.w, lo1);
    size_t off = (size_t)w * AS_STRIDE + 2 * lane;
    *reinterpret_cast<uint2*>(g_aggHi + off) = make_uint2(hi0, hi1);
    *reinterpret_cast<uint2*>(g_aggLo + off) = make_uint2(lo0, lo1);
}

// ---------------------------------------------------------------------------
// fp16x3 tensor GEMM, all-cp.async staging:
// y[M,128] = epi( A @ W + bias (+res) (+deg*dvec) ), A pre-split in g_aggHi/Lo
// ---------------------------------------------------------------------------
#define AS_WORDS  (64 * AS_STRIDE)                    // 4352
#define A_TILE_BYTES (AS_WORDS * 4)                   // 17408
#define SMEM_BYTES ((2 * AS_WORDS + 2 * WS_WORDS) * 4)

__device__ __forceinline__ void mma16(float c[4], const unsigned a[4], const unsigned b[2])
{
    asm volatile(
        "mma.sync.aligned.m16n8k16.row.col.f32.f16.f16.f32 "
        "{%0,%1,%2,%3}, {%4,%5,%6,%7}, {%8,%9}, {%0,%1,%2,%3};"
        : "+f"(c[0]), "+f"(c[1]), "+f"(c[2]), "+f"(c[3])
        : "r"(a[0]), "r"(a[1]), "r"(a[2]), "r"(a[3]), "r"(b[0]), "r"(b[1]));
}

template<bool RELU, bool HAS_RES, bool HAS_DEG>
__global__ __launch_bounds__(256, 2)
void gemm128_s(const unsigned* __restrict__ Whi, const unsigned* __restrict__ Wlo,
               const float* __restrict__ bias,
               const float* __restrict__ res,
               const int* __restrict__ degp, const float* __restrict__ dvec,
               float* __restrict__ out, int M)
{
    extern __shared__ unsigned sm[];
    unsigned* As_hi = sm;
    unsigned* As_lo = sm + AS_WORDS;
    unsigned* Ws_hi = sm + 2 * AS_WORDS;
    unsigned* Ws_lo = sm + 2 * AS_WORDS + WS_WORDS;

    const int tid    = threadIdx.x;
    const int lane   = tid & 31;
    const int wid    = tid >> 5;
    const int warp_m = wid & 1;
    const int warp_n = wid >> 1;
    const int grp    = lane >> 2;
    const int tig    = lane & 3;
    const int row0   = blockIdx.x * 64;

    // ---- all staging via cp.async (zero register dependency) ----
    {
        unsigned sa_hi = (unsigned)__cvta_generic_to_shared(As_hi);
        unsigned sa_lo = (unsigned)__cvta_generic_to_shared(As_lo);
        const char* ga_hi = (const char*)(g_aggHi + (size_t)row0 * AS_STRIDE);
        const char* ga_lo = (const char*)(g_aggLo + (size_t)row0 * AS_STRIDE);
        // A: 17408 B per half = 4 x 4096 + 1024
        #pragma unroll
        for (int i = 0; i < 4; i++) {
            int off = (tid + i * 256) * 16;
            asm volatile("cp.async.cg.shared.global [%0], [%1], 16;"
                         :: "r"(sa_hi + off), "l"(ga_hi + off));
            asm volatile("cp.async.cg.shared.global [%0], [%1], 16;"
                         :: "r"(sa_lo + off), "l"(ga_lo + off));
        }
        if (tid < 64) {
            int off = 4 * 4096 + tid * 16;
            asm volatile("cp.async.cg.shared.global [%0], [%1], 16;"
                         :: "r"(sa_hi + off), "l"(ga_hi + off));
            asm volatile("cp.async.cg.shared.global [%0], [%1], 16;"
                         :: "r"(sa_lo + off), "l"(ga_lo + off));
        }
        unsigned sw_hi = (unsigned)__cvta_generic_to_shared(Ws_hi);
        unsigned sw_lo = (unsigned)__cvta_generic_to_shared(Ws_lo);
        // W: 34816 B per half = 8 x 4096 + 2048
        #pragma unroll
        for (int i = 0; i < 8; i++) {
            int off = (tid + i * 256) * 16;
            asm volatile("cp.async.cg.shared.global [%0], [%1], 16;"
                         :: "r"(sw_hi + off), "l"((const char*)Whi + off));
            asm volatile("cp.async.cg.shared.global [%0], [%1], 16;"
                         :: "r"(sw_lo + off), "l"((const char*)Wlo + off));
        }
        if (tid < 128) {
            int off = 8 * 4096 + tid * 16;
            asm volatile("cp.async.cg.shared.global [%0], [%1], 16;"
                         :: "r"(sw_hi + off), "l"((const char*)Whi + off));
            asm volatile("cp.async.cg.shared.global [%0], [%1], 16;"
                         :: "r"(sw_lo + off), "l"((const char*)Wlo + off));
        }
        asm volatile("cp.async.commit_group;");
        asm volatile("cp.async.wait_group 0;");
    }
    __syncthreads();

    float acc[2][4][4];
    #pragma unroll
    for (int i = 0; i < 2; i++)
        #pragma unroll
        for (int j = 0; j < 4; j++)
            #pragma unroll
            for (int c = 0; c < 4; c++) acc[i][j][c] = 0.f;

    #pragma unroll
    for (int kw0 = 0; kw0 < 64; kw0 += 8) {
        unsigned ah[2][4], al[2][4];
        #pragma unroll
        for (int i = 0; i < 2; i++) {
            int r = warp_m * 32 + i * 16 + grp;
            int b0 = r * AS_STRIDE + kw0 + tig;
            int b8 = (r + 8) * AS_STRIDE + kw0 + tig;
            ah[i][0] = As_hi[b0];     al[i][0] = As_lo[b0];
            ah[i][1] = As_hi[b8];     al[i][1] = As_lo[b8];
            ah[i][2] = As_hi[b0 + 4]; al[i][2] = As_lo[b0 + 4];
            ah[i][3] = As_hi[b8 + 4]; al[i][3] = As_lo[b8 + 4];
        }
        unsigned bh[4][2], bl[4][2];
        #pragma unroll
        for (int j = 0; j < 4; j++) {
            int n = warp_n * 32 + j * 8 + grp;
            int t0 = (kw0 + tig) * WS_STRIDE + n;
            int t4 = (kw0 + tig + 4) * WS_STRIDE + n;
            bh[j][0] = Ws_hi[t0];  bl[j][0] = Ws_lo[t0];
            bh[j][1] = Ws_hi[t4];  bl[j][1] = Ws_lo[t4];
        }
        #pragma unroll
        for (int i = 0; i < 2; i++)
            #pragma unroll
            for (int j = 0; j < 4; j++) {
                mma16(acc[i][j], ah[i], bh[j]);
                mma16(acc[i][j], ah[i], bl[j]);
                mma16(acc[i][j], al[i], bh[j]);
            }
    }

    #pragma unroll
    for (int j = 0; j < 4; j++) {
        int col = warp_n * 32 + j * 8 + tig * 2;
        float2 bv = *reinterpret_cast<const float2*>(bias + col);
        float2 dv = make_float2(0.f, 0.f);
        if (HAS_DEG) dv = *reinterpret_cast<const float2*>(dvec + col);
        #pragma unroll
        for (int i = 0; i < 2; i++) {
            int rbase = row0 + warp_m * 32 + i * 16 + grp;
            #pragma unroll
            for (int half = 0; half < 2; half++) {
                int r = rbase + half * 8;
                if (r >= M) continue;
                float2 v;
                v.x = acc[i][j][half * 2 + 0] + bv.x;
                v.y = acc[i][j][half * 2 + 1] + bv.y;
                if (HAS_DEG) {
                    float dg = (float)degp[r];
                    v.x += dg * dv.x; v.y += dg * dv.y;
                }
                if (HAS_RES) {
                    float2 rr = *reinterpret_cast<const float2*>(res + (size_t)r * 128 + col);
                    v.x += rr.x; v.y += rr.y;
                }
                if (RELU) { v.x = fmaxf(v.x, 0.f); v.y = fmaxf(v.y, 0.f); }
                *reinterpret_cast<float2*>(out + (size_t)r * 128 + col) = v;
            }
        }
    }
}

// ---------------------------------------------------------------------------

extern "C" void kernel_launch(void* const* d_in, const int* in_sizes, int n_in,
                              void* d_out, int out_size)
{
    const float* x     = (const float*)d_in[0];
    const float* Wm    = (const float*)d_in[1];
    const float* bm    = (const float*)d_in[2];
    const float* Wn2s0 = (const float*)d_in[3];
    const float* bn2s0 = (const float*)d_in[4];
    const float* Ws2n0 = (const float*)d_in[5];
    const float* bs2n0 = (const float*)d_in[6];
    const float* Wn2s1 = (const float*)d_in[7];
    const float* bn2s1 = (const float*)d_in[8];
    const float* Ws2n1 = (const float*)d_in[9];
    const float* bs2n1 = (const float*)d_in[10];
    const int* nei = (const int*)d_in[11];
    const int* r0  = (const int*)d_in[12];
    const int* c0  = (const int*)d_in[13];
    const int* r1  = (const int*)d_in[14];
    const int* c1  = (const int*)d_in[15];
    float* out = (float*)d_out;

    float *h, *h1, *sub, *dvec;
    unsigned *whi, *wlo;
    int *cnt, *slNE, *slS0, *slS1, *slN0, *slN1;
    cudaGetSymbolAddress((void**)&h,    g_h);
    cudaGetSymbolAddress((void**)&h1,   g_h1);
    cudaGetSymbolAddress((void**)&sub,  g_sub);
    cudaGetSymbolAddress((void**)&dvec, g_dvec);
    cudaGetSymbolAddress((void**)&whi,  g_Whi);
    cudaGetSymbolAddress((void**)&wlo,  g_Wlo);
    cudaGetSymbolAddress((void**)&cnt,  g_cnt);
    cudaGetSymbolAddress((void**)&slNE, g_slotNE);
    cudaGetSymbolAddress((void**)&slS0, g_slotS2N0);
    cudaGetSymbolAddress((void**)&slS1, g_slotS2N1);
    cudaGetSymbolAddress((void**)&slN0, g_slotN2S0);
    cudaGetSymbolAddress((void**)&slN1, g_slotN2S1);

    cudaFuncSetAttribute(gemm128_s<true,  false, false>,
                         cudaFuncAttributeMaxDynamicSharedMemorySize, SMEM_BYTES);
    cudaFuncSetAttribute(gemm128_s<false, true,  true>,
                         cudaFuncAttributeMaxDynamicSharedMemorySize, SMEM_BYTES);

    const int GB_N = (NN + 63) / 64;
    const int RB_N = (NN * 32 + 255) / 256;
    const int RB_S = (NS * 32 + 255) / 256;
    const int FB   = (NE + 255) / 256;

    // Prep
    cudaMemsetAsync(cnt, 0, (3 * NN + 2 * NS) * sizeof(int));
    fill_all_k<<<dim3(FB, 5), 256>>>(nei, r0, c0, r1, c1);
    wcdvec_k<<<dim3(129, 2), 128>>>(Wn2s0, Ws2n0, bn2s0, Wn2s1, Ws2n1, bn2s1);
    convert_w_k<<<dim3(32, 3), 256>>>(Wm);

    // message_neighbor: aggHL = split(x + segsum(x)); h = relu(agg @ Wm + bm)
    reduce_hl_k<true><<<RB_N, 256>>>(x, x, cnt + C_NE, slNE, NN);
    gemm128_s<true, false, false><<<GB_N, 256, SMEM_BYTES>>>(
        whi + 0 * WS_WORDS, wlo + 0 * WS_WORDS, bm, nullptr,
        nullptr, nullptr, h, NN);

    // level 0
    reduce_k<<<RB_S, 256>>>(h, cnt + C_N2S0, slN0, sub, NS);
    reduce_hl_k<false><<<RB_N, 256>>>(sub, nullptr, cnt + C_S2N0, slS0, NN);
    gemm128_s<false, true, true><<<GB_N, 256, SMEM_BYTES>>>(
        whi + 1 * WS_WORDS, wlo + 1 * WS_WORDS, bs2n0, h,
        cnt + C_S2N0, dvec + 0, h1, NN);

    // level 1
    reduce_k<<<RB_S, 256>>>(h1, cnt + C_N2S1, slN1, sub, NS);
    reduce_hl_k<false><<<RB_N, 256>>>(sub, nullptr, cnt + C_S2N1, slS1, NN);
    gemm128_s<false, true, true><<<GB_N, 256, SMEM_BYTES>>>(
        whi + 2 * WS_WORDS, wlo + 2 * WS_WORDS, bs2n1, h1,
        cnt + C_S2N1, dvec + 128, out, NN);
}

// round 15
// speedup vs baseline: 1.1777x; 1.0326x over previous
#include <cuda_runtime.h>
#include <cuda_fp16.h>
#include <cuda_bf16.h>

#define D 128
#define NN 50000
#define NS 20000
#define NE 600000
#define ES 120000
#define CAP 64
#define NN_PAD 50048

// Feature buffers (fp32)
__device__ float g_h   [(size_t)NN * D];
__device__ float g_h1  [(size_t)NN * D];
__device__ float g_sub [(size_t)NS * D];

// GEMM A operand pre-split fp16 hi/lo, padded layout [w*68 + kw]
#define AS_STRIDE 68
__device__ unsigned g_aggHi[(size_t)NN_PAD * AS_STRIDE];
__device__ unsigned g_aggLo[(size_t)NN_PAD * AS_STRIDE];

// Combined weights + deg-bias vectors
__device__ float g_Wc[2 * 128 * 128];
__device__ float g_dvec[2 * 128];

// Bucket CSR scratch
#define C_NE   0
#define C_S2N0 (NN)
#define C_S2N1 (2 * NN)
#define C_N2S0 (3 * NN)
#define C_N2S1 (3 * NN + NS)
#define CNT_TOT (3 * NN + 2 * NS)
__device__ int g_cnt[CNT_TOT];
__device__ int g_slotNE  [(size_t)NN * CAP];
__device__ int g_slotS2N0[(size_t)NN * CAP];
__device__ int g_slotS2N1[(size_t)NN * CAP];
__device__ int g_slotN2S0[(size_t)NS * CAP];
__device__ int g_slotN2S1[(size_t)NS * CAP];

// fp16 hi/lo W splits: 0=Wm, 1=Wc0, 2=Wc1
#define WS_STRIDE 136
#define WS_WORDS  (64 * WS_STRIDE)
__device__ unsigned g_Whi[3 * WS_WORDS];
__device__ unsigned g_Wlo[3 * WS_WORDS];

// ---------------------------------------------------------------------------
__device__ __forceinline__ unsigned pack_split(float x0, float x1, unsigned& lo)
{
    __half h0 = __float2half_rn(x0), h1 = __float2half_rn(x1);
    __half l0 = __float2half_rn(x0 - __half2float(h0));
    __half l1 = __float2half_rn(x1 - __half2float(h1));
    __half2 lv = __halves2half2(l0, l1);
    __half2 hv = __halves2half2(h0, h1);
    lo = *reinterpret_cast<unsigned*>(&lv);
    return *reinterpret_cast<unsigned*>(&hv);
}

// ---------------------------------------------------------------------------
// Prep kernels
// ---------------------------------------------------------------------------
__global__ void wcdvec_k(const float* __restrict__ A0, const float* __restrict__ B0,
                         const float* __restrict__ b0,
                         const float* __restrict__ A1, const float* __restrict__ B1,
                         const float* __restrict__ b1)
{
    __shared__ float a[128];
    int lvl = blockIdx.y;
    const float* A = lvl ? A1 : A0;
    const float* B = lvl ? B1 : B0;
    const float* b = lvl ? b1 : b0;
    int i = blockIdx.x, j = threadIdx.x;
    a[j] = (i < 128) ? A[i * 128 + j] : b[j];
    __syncthreads();
    float acc = 0.f;
    #pragma unroll 8
    for (int k = 0; k < 128; k++) acc += a[k] * B[k * 128 + j];
    if (i < 128) g_Wc[lvl * 16384 + i * 128 + j] = acc;
    else         g_dvec[lvl * 128 + j] = acc;
}

__global__ void convert_w_k(const float* __restrict__ Wm)
{
    int m = blockIdx.y;
    const float* W = (m == 0) ? Wm : (g_Wc + (m - 1) * 16384);
    unsigned* dhi = g_Whi + m * WS_WORDS;
    unsigned* dlo = g_Wlo + m * WS_WORDS;
    int e = blockIdx.x * blockDim.x + threadIdx.x;
    int kw = e >> 7, n = e & 127;
    float w0 = W[(size_t)(2 * kw)     * 128 + n];
    float w1 = W[(size_t)(2 * kw + 1) * 128 + n];
    unsigned lo;
    unsigned hi = pack_split(w0, w1, lo);
    dhi[kw * WS_STRIDE + n] = hi;
    dlo[kw * WS_STRIDE + n] = lo;
}

__global__ void zero_cnt_k()
{
    int i = blockIdx.x * blockDim.x + threadIdx.x;
    if (i < CNT_TOT) g_cnt[i] = 0;
}

// ---------------------------------------------------------------------------
// Merged bucket fill (PDL: index loads pre-sync, atomics post-sync)
// ---------------------------------------------------------------------------
__global__ void fill_all_k(const int* __restrict__ nei,
                           const int* __restrict__ r0, const int* __restrict__ c0,
                           const int* __restrict__ r1, const int* __restrict__ c1)
{
    int e = blockIdx.x * blockDim.x + threadIdx.x;
    int ph = blockIdx.y;
    const int* gi; const int* si; int cbase; int* slot; int n;
    switch (ph) {
        case 0:  gi = nei; si = nei + NE; cbase = C_NE;   slot = g_slotNE;   n = NE; break;
        case 1:  gi = r0;  si = c0;       cbase = C_N2S0; slot = g_slotN2S0; n = ES; break;
        case 2:  gi = c0;  si = r0;       cbase = C_S2N0; slot = g_slotS2N0; n = ES; break;
        case 3:  gi = r1;  si = c1;       cbase = C_N2S1; slot = g_slotN2S1; n = ES; break;
        default: gi = c1;  si = r1;       cbase = C_S2N1; slot = g_slotS2N1; n = ES; break;
    }
    if (e >= n) return;
    int s = si[e];
    int g = gi[e];
    cudaGridDependencySynchronize();     // wait zero_cnt
    int p = atomicAdd(&g_cnt[cbase + s], 1);
    if (p < CAP) slot[(size_t)s * CAP + p] = g;
}

// ---------------------------------------------------------------------------
// Warp-per-node gather reduce -> fp32 (n2s phases).
// Predecessor produced feat; cnt/slot are older -> deg read pre-sync.
// ---------------------------------------------------------------------------
__global__ void reduce_k(const float* __restrict__ feat,
                         const int* __restrict__ cnt, const int* __restrict__ slot,
                         float* __restrict__ out, int nNodes)
{
    cudaTriggerProgrammaticLaunchCompletion();
    int t = blockIdx.x * blockDim.x + threadIdx.x;
    int w = t >> 5, lane = t & 31;
    if (w >= nNodes) return;
    int deg = cnt[w];
    if (deg > CAP) deg = CAP;
    const int* sl = slot + (size_t)w * CAP;
    cudaGridDependencySynchronize();     // wait feat producer
    float4 a0 = make_float4(0.f, 0.f, 0.f, 0.f), a1 = a0, a2 = a0, a3 = a0;
    int j = 0;
    for (; j + 4 <= deg; j += 4) {
        int s0 = sl[j], s1 = sl[j + 1], s2 = sl[j + 2], s3 = sl[j + 3];
        float4 v0 = reinterpret_cast<const float4*>(feat + (size_t)s0 * D)[lane];
        float4 v1 = reinterpret_cast<const float4*>(feat + (size_t)s1 * D)[lane];
        float4 v2 = reinterpret_cast<const float4*>(feat + (size_t)s2 * D)[lane];
        float4 v3 = reinterpret_cast<const float4*>(feat + (size_t)s3 * D)[lane];
        a0.x += v0.x; a0.y += v0.y; a0.z += v0.z; a0.w += v0.w;
        a1.x += v1.x; a1.y += v1.y; a1.z += v1.z; a1.w += v1.w;
        a2.x += v2.x; a2.y += v2.y; a2.z += v2.z; a2.w += v2.w;
        a3.x += v3.x; a3.y += v3.y; a3.z += v3.z; a3.w += v3.w;
    }
    for (; j < deg; j++) {
        float4 v = reinterpret_cast<const float4*>(feat + (size_t)sl[j] * D)[lane];
        a0.x += v.x; a0.y += v.y; a0.z += v.z; a0.w += v.w;
    }
    float4 r;
    r.x = (a0.x + a1.x) + (a2.x + a3.x);
    r.y = (a0.y + a1.y) + (a2.y + a3.y);
    r.z = (a0.z + a1.z) + (a2.z + a3.z);
    r.w = (a0.w + a1.w) + (a2.w + a3.w);
    reinterpret_cast<float4*>(out + (size_t)w * D)[lane] = r;
}

// ---------------------------------------------------------------------------
// Gather reduce -> pre-split fp16 hi/lo (GEMM A feeds).
// SYNC_FIRST: predecessor is fill (cnt/slot dependent) -> sync before cnt.
// else: predecessor produced feat -> deg pre-sync, gathers post-sync.
// ---------------------------------------------------------------------------
template<bool HAS_BASE, bool SYNC_FIRST>
__global__ void reduce_hl_k(const float* __restrict__ feat,
                            const float* __restrict__ base,
                            const int* __restrict__ cnt, const int* __restrict__ slot,
                            int nNodes)
{
    cudaTriggerProgrammaticLaunchCompletion();
    int t = blockIdx.x * blockDim.x + threadIdx.x;
    int w = t >> 5, lane = t & 31;
    if (w >= nNodes) return;
    if (SYNC_FIRST) cudaGridDependencySynchronize();
    int deg = cnt[w];
    if (deg > CAP) deg = CAP;
    const int* sl = slot + (size_t)w * CAP;
    if (!SYNC_FIRST) cudaGridDependencySynchronize();
    float4 a0 = make_float4(0.f, 0.f, 0.f, 0.f), a1 = a0, a2 = a0, a3 = a0;
    if (HAS_BASE)
        a0 = reinterpret_cast<const float4*>(base + (size_t)w * D)[lane];
    int j = 0;
    for (; j + 4 <= deg; j += 4) {
        int s0 = sl[j], s1 = sl[j + 1], s2 = sl[j + 2], s3 = sl[j + 3];
        float4 v0 = reinterpret_cast<const float4*>(feat + (size_t)s0 * D)[lane];
        float4 v1 = reinterpret_cast<const float4*>(feat + (size_t)s1 * D)[lane];
        float4 v2 = reinterpret_cast<const float4*>(feat + (size_t)s2 * D)[lane];
        float4 v3 = reinterpret_cast<const float4*>(feat + (size_t)s3 * D)[lane];
        a0.x += v0.x; a0.y += v0.y; a0.z += v0.z; a0.w += v0.w;
        a1.x += v1.x; a1.y += v1.y; a1.z += v1.z; a1.w += v1.w;
        a2.x += v2.x; a2.y += v2.y; a2.z += v2.z; a2.w += v2.w;
        a3.x += v3.x; a3.y += v3.y; a3.z += v3.z; a3.w += v3.w;
    }
    for (; j < deg; j++) {
        float4 v = reinterpret_cast<const float4*>(feat + (size_t)sl[j] * D)[lane];
        a0.x += v.x; a0.y += v.y; a0.z += v.z; a0.w += v.w;
    }
    float4 r;
    r.x = (a0.x + a1.x) + (a2.x + a3.x);
    r.y = (a0.y + a1.y) + (a2.y + a3.y);
    r.z = (a0.z + a1.z) + (a2.z + a3.z);
    r.w = (a0.w + a1.w) + (a2.w + a3.w);
    unsigned lo0, lo1;
    unsigned hi0 = pack_split(r.x, r.y, lo0);
    unsigned hi1 = pack_split(r.z, r.w, lo1);
    size_t off = (size_t)w * AS_STRIDE + 2 * lane;
    *reinterpret_cast<uint2*>(g_aggHi + off) = make_uint2(hi0, hi1);
    *reinterpret_cast<uint2*>(g_aggLo + off) = make_uint2(lo0, lo1);
}

// ---------------------------------------------------------------------------
// fp16x3 tensor GEMM: W staged pre-sync (PDL overlap), A staged post-sync
// ---------------------------------------------------------------------------
#define AS_WORDS  (64 * AS_STRIDE)
#define SMEM_BYTES ((2 * AS_WORDS + 2 * WS_WORDS) * 4)

__device__ __forceinline__ void mma16(float c[4], const unsigned a[4], const unsigned b[2])
{
    asm volatile(
        "mma.sync.aligned.m16n8k16.row.col.f32.f16.f16.f32 "
        "{%0,%1,%2,%3}, {%4,%5,%6,%7}, {%8,%9}, {%0,%1,%2,%3};"
        : "+f"(c[0]), "+f"(c[1]), "+f"(c[2]), "+f"(c[3])
        : "r"(a[0]), "r"(a[1]), "r"(a[2]), "r"(a[3]), "r"(b[0]), "r"(b[1]));
}

template<bool RELU, bool HAS_RES, bool HAS_DEG>
__global__ __launch_bounds__(256, 2)
void gemm128_s(const unsigned* __restrict__ Whi, const unsigned* __restrict__ Wlo,
               const float* __restrict__ bias,
               const float* __restrict__ res,
               const int* __restrict__ degp, const float* __restrict__ dvec,
               float* __restrict__ out, int M)
{
    cudaTriggerProgrammaticLaunchCompletion();
    extern __shared__ unsigned sm[];
    unsigned* As_hi = sm;
    unsigned* As_lo = sm + AS_WORDS;
    unsigned* Ws_hi = sm + 2 * AS_WORDS;
    unsigned* Ws_lo = sm + 2 * AS_WORDS + WS_WORDS;

    const int tid    = threadIdx.x;
    const int lane   = tid & 31;
    const int wid    = tid >> 5;
    const int warp_m = wid & 1;
    const int warp_n = wid >> 1;
    const int grp    = lane >> 2;
    const int tig    = lane & 3;
    const int row0   = blockIdx.x * 64;

    // ---- W staging pre-sync (depends only on convert_w, complete by construction)
    {
        unsigned sw_hi = (unsigned)__cvta_generic_to_shared(Ws_hi);
        unsigned sw_lo = (unsigned)__cvta_generic_to_shared(Ws_lo);
        #pragma unroll
        for (int i = 0; i < 8; i++) {
            int off = (tid + i * 256) * 16;
            asm volatile("cp.async.cg.shared.global [%0], [%1], 16;"
                         :: "r"(sw_hi + off), "l"((const char*)Whi + off));
            asm volatile("cp.async.cg.shared.global [%0], [%1], 16;"
                         :: "r"(sw_lo + off), "l"((const char*)Wlo + off));
        }
        if (tid < 128) {
            int off = 8 * 4096 + tid * 16;
            asm volatile("cp.async.cg.shared.global [%0], [%1], 16;"
                         :: "r"(sw_hi + off), "l"((const char*)Whi + off));
            asm volatile("cp.async.cg.shared.global [%0], [%1], 16;"
                         :: "r"(sw_lo + off), "l"((const char*)Wlo + off));
        }
    }

    cudaGridDependencySynchronize();   // wait A producer (reduce_hl)

    // ---- A staging post-sync
    {
        unsigned sa_hi = (unsigned)__cvta_generic_to_shared(As_hi);
        unsigned sa_lo = (unsigned)__cvta_generic_to_shared(As_lo);
        const char* ga_hi = (const char*)(g_aggHi + (size_t)row0 * AS_STRIDE);
        const char* ga_lo = (const char*)(g_aggLo + (size_t)row0 * AS_STRIDE);
        #pragma unroll
        for (int i = 0; i < 4; i++) {
            int off = (tid + i * 256) * 16;
            asm volatile("cp.async.cg.shared.global [%0], [%1], 16;"
                         :: "r"(sa_hi + off), "l"(ga_hi + off));
            asm volatile("cp.async.cg.shared.global [%0], [%1], 16;"
                         :: "r"(sa_lo + off), "l"(ga_lo + off));
        }
        if (tid < 64) {
            int off = 4 * 4096 + tid * 16;
            asm volatile("cp.async.cg.shared.global [%0], [%1], 16;"
                         :: "r"(sa_hi + off), "l"(ga_hi + off));
            asm volatile("cp.async.cg.shared.global [%0], [%1], 16;"
                         :: "r"(sa_lo + off), "l"(ga_lo + off));
        }
        asm volatile("cp.async.commit_group;");
        asm volatile("cp.async.wait_group 0;");
    }
    __syncthreads();

    float acc[2][4][4];
    #pragma unroll
    for (int i = 0; i < 2; i++)
        #pragma unroll
        for (int j = 0; j < 4; j++)
            #pragma unroll
            for (int c = 0; c < 4; c++) acc[i][j][c] = 0.f;

    #pragma unroll
    for (int kw0 = 0; kw0 < 64; kw0 += 8) {
        unsigned ah[2][4], al[2][4];
        #pragma unroll
        for (int i = 0; i < 2; i++) {
            int r = warp_m * 32 + i * 16 + grp;
            int b0 = r * AS_STRIDE + kw0 + tig;
            int b8 = (r + 8) * AS_STRIDE + kw0 + tig;
            ah[i][0] = As_hi[b0];     al[i][0] = As_lo[b0];
            ah[i][1] = As_hi[b8];     al[i][1] = As_lo[b8];
            ah[i][2] = As_hi[b0 + 4]; al[i][2] = As_lo[b0 + 4];
            ah[i][3] = As_hi[b8 + 4]; al[i][3] = As_lo[b8 + 4];
        }
        unsigned bh[4][2], bl[4][2];
        #pragma unroll
        for (int j = 0; j < 4; j++) {
            int n = warp_n * 32 + j * 8 + grp;
            int t0 = (kw0 + tig) * WS_STRIDE + n;
            int t4 = (kw0 + tig + 4) * WS_STRIDE + n;
            bh[j][0] = Ws_hi[t0];  bl[j][0] = Ws_lo[t0];
            bh[j][1] = Ws_hi[t4];  bl[j][1] = Ws_lo[t4];
        }
        #pragma unroll
        for (int i = 0; i < 2; i++)
            #pragma unroll
            for (int j = 0; j < 4; j++) {
                mma16(acc[i][j], ah[i], bh[j]);
                mma16(acc[i][j], ah[i], bl[j]);
                mma16(acc[i][j], al[i], bh[j]);
            }
    }

    #pragma unroll
    for (int j = 0; j < 4; j++) {
        int col = warp_n * 32 + j * 8 + tig * 2;
        float2 bv = *reinterpret_cast<const float2*>(bias + col);
        float2 dv = make_float2(0.f, 0.f);
        if (HAS_DEG) dv = *reinterpret_cast<const float2*>(dvec + col);
        #pragma unroll
        for (int i = 0; i < 2; i++) {
            int rbase = row0 + warp_m * 32 + i * 16 + grp;
            #pragma unroll
            for (int half = 0; half < 2; half++) {
                int r = rbase + half * 8;
                if (r >= M) continue;
                float2 v;
                v.x = acc[i][j][half * 2 + 0] + bv.x;
                v.y = acc[i][j][half * 2 + 1] + bv.y;
                if (HAS_DEG) {
                    float dg = (float)degp[r];
                    v.x += dg * dv.x; v.y += dg * dv.y;
                }
                if (HAS_RES) {
                    float2 rr = *reinterpret_cast<const float2*>(res + (size_t)r * 128 + col);
                    v.x += rr.x; v.y += rr.y;
                }
                if (RELU) { v.x = fmaxf(v.x, 0.f); v.y = fmaxf(v.y, 0.f); }
                *reinterpret_cast<float2*>(out + (size_t)r * 128 + col) = v;
            }
        }
    }
}

// ---------------------------------------------------------------------------
template <typename F, typename... Args>
static inline void pdl_launch(F f, dim3 grid, dim3 block, size_t smem, Args... args)
{
    cudaLaunchConfig_t cfg{};
    cfg.gridDim = grid; cfg.blockDim = block;
    cfg.dynamicSmemBytes = smem; cfg.stream = 0;
    cudaLaunchAttribute attr[1];
    attr[0].id = cudaLaunchAttributeProgrammaticStreamSerialization;
    attr[0].val.programmaticStreamSerializationAllowed = 1;
    cfg.attrs = attr; cfg.numAttrs = 1;
    cudaLaunchKernelEx(&cfg, f, args...);
}

extern "C" void kernel_launch(void* const* d_in, const int* in_sizes, int n_in,
                              void* d_out, int out_size)
{
    const float* x     = (const float*)d_in[0];
    const float* Wm    = (const float*)d_in[1];
    const float* bm    = (const float*)d_in[2];
    const float* Wn2s0 = (const float*)d_in[3];
    const float* bn2s0 = (const float*)d_in[4];
    const float* Ws2n0 = (const float*)d_in[5];
    const float* bs2n0 = (const float*)d_in[6];
    const float* Wn2s1 = (const float*)d_in[7];
    const float* bn2s1 = (const float*)d_in[8];
    const float* Ws2n1 = (const float*)d_in[9];
    const float* bs2n1 = (const float*)d_in[10];
    const int* nei = (const int*)d_in[11];
    const int* r0  = (const int*)d_in[12];
    const int* c0  = (const int*)d_in[13];
    const int* r1  = (const int*)d_in[14];
    const int* c1  = (const int*)d_in[15];
    float* out = (float*)d_out;

    float *h, *h1, *sub, *dvec;
    unsigned *whi, *wlo;
    int *cnt, *slNE, *slS0, *slS1, *slN0, *slN1;
    cudaGetSymbolAddress((void**)&h,    g_h);
    cudaGetSymbolAddress((void**)&h1,   g_h1);
    cudaGetSymbolAddress((void**)&sub,  g_sub);
    cudaGetSymbolAddress((void**)&dvec, g_dvec);
    cudaGetSymbolAddress((void**)&whi,  g_Whi);
    cudaGetSymbolAddress((void**)&wlo,  g_Wlo);
    cudaGetSymbolAddress((void**)&cnt,  g_cnt);
    cudaGetSymbolAddress((void**)&slNE, g_slotNE);
    cudaGetSymbolAddress((void**)&slS0, g_slotS2N0);
    cudaGetSymbolAddress((void**)&slS1, g_slotS2N1);
    cudaGetSymbolAddress((void**)&slN0, g_slotN2S0);
    cudaGetSymbolAddress((void**)&slN1, g_slotN2S1);

    cudaFuncSetAttribute(gemm128_s<true,  false, false>,
                         cudaFuncAttributeMaxDynamicSharedMemorySize, SMEM_BYTES);
    cudaFuncSetAttribute(gemm128_s<false, true,  true>,
                         cudaFuncAttributeMaxDynamicSharedMemorySize, SMEM_BYTES);

    const int GB_N = (NN + 63) / 64;
    const int RB_N = (NN * 32 + 255) / 256;
    const int RB_S = (NS * 32 + 255) / 256;
    const int FB   = (NE + 255) / 256;
    const int ZB   = (CNT_TOT + 255) / 256;

    // Prep: weights (normal), zero (normal), fill (PDL over zero)
    wcdvec_k<<<dim3(129, 2), 128>>>(Wn2s0, Ws2n0, bn2s0, Wn2s1, Ws2n1, bn2s1);
    convert_w_k<<<dim3(32, 3), 256>>>(Wm);
    zero_cnt_k<<<ZB, 256>>>();
    pdl_launch(fill_all_k, dim3(FB, 5), dim3(256), 0, nei, r0, c0, r1, c1);

    // message_neighbor
    pdl_launch(reduce_hl_k<true, true>, dim3(RB_N), dim3(256), 0,
               x, x, (const int*)(cnt + C_NE), (const int*)slNE, NN);
    pdl_launch(gemm128_s<true, false, false>, dim3(GB_N), dim3(256), (size_t)SMEM_BYTES,
               (const unsigned*)(whi + 0 * WS_WORDS), (const unsigned*)(wlo + 0 * WS_WORDS),
               (const float*)bm, (const float*)nullptr,
               (const int*)nullptr, (const float*)nullptr, h, NN);

    // level 0
    pdl_launch(reduce_k, dim3(RB_S), dim3(256), 0,
               (const float*)h, (const int*)(cnt + C_N2S0), (const int*)slN0, sub, NS);
    pdl_launch(reduce_hl_k<false, false>, dim3(RB_N), dim3(256), 0,
               (const float*)sub, (const float*)nullptr,
               (const int*)(cnt + C_S2N0), (const int*)slS0, NN);
    pdl_launch(gemm128_s<false, true, true>, dim3(GB_N), dim3(256), (size_t)SMEM_BYTES,
               (const unsigned*)(whi + 1 * WS_WORDS), (const unsigned*)(wlo + 1 * WS_WORDS),
               (const float*)bs2n0, (const float*)h,
               (const int*)(cnt + C_S2N0), (const float*)(dvec + 0), h1, NN);

    // level 1
    pdl_launch(reduce_k, dim3(RB_S), dim3(256), 0,
               (const float*)h1, (const int*)(cnt + C_N2S1), (const int*)slN1, sub, NS);
    pdl_launch(reduce_hl_k<false, false>, dim3(RB_N), dim3(256), 0,
               (const float*)sub, (const float*)nullptr,
               (const int*)(cnt + C_S2N1), (const int*)slS1, NN);
    pdl_launch(gemm128_s<false, true, true>, dim3(GB_N), dim3(256), (size_t)SMEM_BYTES,
               (const unsigned*)(whi + 2 * WS_WORDS), (const unsigned*)(wlo + 2 * WS_WORDS),
               (const float*)bs2n1, (const float*)h1,
               (const int*)(cnt + C_S2N1), (const float*)(dvec + 128), out, NN);
}